// round 8
// baseline (speedup 1.0000x reference)
#include <cuda_runtime.h>

// ---------------------------------------------------------------------------
// GIN encoder. Bucketed-CSR pipeline + algebraic BN fold:
//   memset -> 4x weight-copy-to-constant -> fill ->
//   [agg0 -> mlp0 -> ow0] -> [agg1(BN0 folded) -> mlp1 -> ow1]
//   out[g] = scale * poolsum_preBN[g] + cnt[g] * shift
//   hin1   = sc0*(h0[n] + sum h0[src]) + (1+deg)*sh0     (x0 never stored)
// Weights live in __constant__ (64KB exactly: W1_0|W2_0|W1_1|W2_1).
// ---------------------------------------------------------------------------

#define MAX_N 100000
#define MAX_G 1024
#define DIM 64
#define BN_EPS 1e-5f
#define SLOTS 64

// per-layer reduction buffer: pool[MAX_G*DIM] | sumsq[DIM] | totsum[DIM]
#define PS_FLOATS (MAX_G * DIM + 2 * DIM)

// single zeroed scratch region: ps0 | ps1 | deg[MAX_N] | cnt[MAX_G]
__device__ __align__(16) unsigned int g_zeroed[2 * PS_FLOATS + MAX_N + MAX_G];
#define DEGP ((int*)g_zeroed + 2 * PS_FLOATS)
#define CNTP (DEGP + MAX_N)

__device__ __align__(16) float g_h0 [MAX_N * DIM];   // layer-0 pre-BN h
__device__ __align__(16) float g_hin[MAX_N * DIM];   // MLP inputs
__device__ __align__(16) int g_srcidx[MAX_N * SLOTS];

// all four 64x64 weight matrices: W1_0 | W2_0 | W1_1 | W2_1 (64KB exactly)
__constant__ __align__(16) float c_W[4 * 4096];

// ---------------- packed f32x2 + tanh helpers (sm_100+) --------------------
static __device__ __forceinline__ unsigned long long ffma2(
    unsigned long long a, unsigned long long b, unsigned long long c) {
    unsigned long long d;
    asm("fma.rn.f32x2 %0, %1, %2, %3;" : "=l"(d) : "l"(a), "l"(b), "l"(c));
    return d;
}
static __device__ __forceinline__ unsigned long long pack2(float x, float y) {
    unsigned long long r;
    asm("mov.b64 %0, {%1, %2};" : "=l"(r) : "f"(x), "f"(y));
    return r;
}
static __device__ __forceinline__ float2 unpack2(unsigned long long v) {
    float2 f;
    asm("mov.b64 {%0, %1}, %2;" : "=f"(f.x), "=f"(f.y) : "l"(v));
    return f;
}
static __device__ __forceinline__ float tanha(float x) {
    float y;
    asm("tanh.approx.f32 %0, %1;" : "=f"(y) : "f"(x));
    return y;
}

// ---------------- bucket fill + graph counts -------------------------------
__global__ void fill_cnt_kernel(const int* __restrict__ ei,
                                const int* __restrict__ batch, int E, int N) {
    int t = blockIdx.x * blockDim.x + threadIdx.x;
    if (t < E) {
        int s = __ldg(ei + t);
        int d = __ldg(ei + E + t);
        int pos = atomicAdd(&DEGP[d], 1);
        if (pos < SLOTS) g_srcidx[d * SLOTS + pos] = s;
    }
    if (t < N) atomicAdd(&CNTP[__ldg(batch + t)], 1);
}

// ---------------- aggregation (gather, no atomics) -------------------------
// 16 lanes per node (float4 columns), 8 nodes per 128-thread block.
// All index chunks prefetched up front (bucket base is compile-known aligned),
// then data loads issue back-to-back -> high MLP.
template <bool AFFINE>
__global__ __launch_bounds__(128) void aggregate_kernel(
    const float* __restrict__ x, float* __restrict__ hout,
    const float* __restrict__ psPrev,
    const float* __restrict__ gamma, const float* __restrict__ beta,
    float invN, int N) {
    int node = blockIdx.x * 8 + (threadIdx.x >> 4);
    int c = threadIdx.x & 15;
    if (node >= N) return;
    int deg = __ldg(&DEGP[node]);
    const float4* x4 = reinterpret_cast<const float4*>(x);
    const int4* idx4 = reinterpret_cast<const int4*>(g_srcidx + node * SLOTS);
    float4 acc = x4[node * 16 + c];

    int nc = deg >> 2;           // full 4-edge chunks
    if (nc > 8) nc = 8;          // cap: 32 prefetched edges
    int4 sidx[8];
#pragma unroll
    for (int q = 0; q < 8; q++)
        if (q < nc) sidx[q] = __ldg(&idx4[q]);
#pragma unroll
    for (int q = 0; q < 8; q++) {
        if (q < nc) {
            float4 v0 = x4[sidx[q].x * 16 + c];
            float4 v1 = x4[sidx[q].y * 16 + c];
            float4 v2 = x4[sidx[q].z * 16 + c];
            float4 v3 = x4[sidx[q].w * 16 + c];
            acc.x += (v0.x + v1.x) + (v2.x + v3.x);
            acc.y += (v0.y + v1.y) + (v2.y + v3.y);
            acc.z += (v0.z + v1.z) + (v2.z + v3.z);
            acc.w += (v0.w + v1.w) + (v2.w + v3.w);
        }
    }
    for (int e = nc * 4; e < deg; e++) {   // remainder (+ rare deg>32 tail)
        int s = __ldg(g_srcidx + node * SLOTS + e);
        float4 v0 = x4[s * 16 + c];
        acc.x += v0.x;
        acc.y += v0.y;
        acc.z += v0.z;
        acc.w += v0.w;
    }

    if (AFFINE) {
        const float4* ss4 = reinterpret_cast<const float4*>(psPrev + MAX_G * DIM);
        const float4* ts4 = reinterpret_cast<const float4*>(psPrev + MAX_G * DIM + DIM);
        float4 ssq = __ldg(&ss4[c]);
        float4 tot = __ldg(&ts4[c]);
        float4 gm = __ldg(&reinterpret_cast<const float4*>(gamma)[c]);
        float4 bt = __ldg(&reinterpret_cast<const float4*>(beta)[c]);
        float f = (float)(1 + deg);
        float mx = tot.x * invN, my = tot.y * invN,
              mz = tot.z * invN, mw = tot.w * invN;
        float scx = gm.x * rsqrtf(ssq.x * invN - mx * mx + BN_EPS);
        float scy = gm.y * rsqrtf(ssq.y * invN - my * my + BN_EPS);
        float scz = gm.z * rsqrtf(ssq.z * invN - mz * mz + BN_EPS);
        float scw = gm.w * rsqrtf(ssq.w * invN - mw * mw + BN_EPS);
        acc.x = acc.x * scx + f * (bt.x - mx * scx);
        acc.y = acc.y * scy + f * (bt.y - my * scy);
        acc.z = acc.z * scz + f * (bt.z - mz * scz);
        acc.w = acc.w * scw + f * (bt.w - mw * scw);
    }
    reinterpret_cast<float4*>(hout)[node * 16 + c] = acc;
}

// ---------------- MLP stage (constant weights, f32x2 FMA, MUFU tanh) -------
template <int WOFS>
static __device__ __forceinline__ void mlp_stage(float* row,
                                                 const float* __restrict__ bias) {
    unsigned long long acc[32];
    const ulonglong2* bp = reinterpret_cast<const ulonglong2*>(bias);
#pragma unroll
    for (int j = 0; j < 16; j++) {
        ulonglong2 b = __ldg(&bp[j]);
        acc[2 * j + 0] = b.x;
        acc[2 * j + 1] = b.y;
    }

    for (int k = 0; k < DIM; k++) {
        float xk = row[k];
        unsigned long long xx = pack2(xk, xk);
        const ulonglong2* Wp =
            reinterpret_cast<const ulonglong2*>(c_W + WOFS + (k << 6));
#pragma unroll
        for (int j = 0; j < 16; j++) {
            ulonglong2 w = Wp[j];
            acc[2 * j + 0] = ffma2(xx, w.x, acc[2 * j + 0]);
            acc[2 * j + 1] = ffma2(xx, w.y, acc[2 * j + 1]);
        }
    }
#pragma unroll
    for (int j = 0; j < 32; j++) {
        float2 v = unpack2(acc[j]);
        row[2 * j + 0] = tanha(v.x);
        row[2 * j + 1] = tanha(v.y);
    }
}

// ---------------- MLP + BN stats + pre-BN pool sums ------------------------
// LAYER selects constant-weight offsets. Rows-only smem (34KB) -> ~5 blocks/SM.
template <int LAYER, bool WRITE_H>
__global__ __launch_bounds__(128) void mlp_kernel(
    const float* __restrict__ hin,
    const float* __restrict__ b1, const float* __restrict__ b2,
    const int* __restrict__ batch, float* __restrict__ hout,
    float* __restrict__ ps, int N) {
    __shared__ float rows[128 * 65];
    __shared__ int bats[128];

    float* pool   = ps;
    float* stats  = ps + MAX_G * DIM;
    float* totsum = ps + MAX_G * DIM + DIM;

    int tid  = threadIdx.x;
    int base = blockIdx.x * 128;
    int node = base + tid;

    bats[tid] = __ldg(batch + (node < N ? node : N - 1));

    float* myrow = rows + tid * 65;
    if (node < N) {
        const float4* h4 = reinterpret_cast<const float4*>(hin);
#pragma unroll
        for (int c = 0; c < 16; c++) {
            float4 v = h4[node * 16 + c];
            myrow[4 * c + 0] = v.x;
            myrow[4 * c + 1] = v.y;
            myrow[4 * c + 2] = v.z;
            myrow[4 * c + 3] = v.w;
        }
        // phases 1-2 touch only this thread's own row: no barrier needed
        mlp_stage<LAYER * 8192 + 0>(myrow, b1);
        mlp_stage<LAYER * 8192 + 4096>(myrow, b2);
    } else {
#pragma unroll
        for (int c = 0; c < DIM; c++) myrow[c] = 0.0f;
    }
    __syncthreads();   // rows + bats complete for cross-thread phase 3

    if (WRITE_H) {
        int gb = base * DIM;
        for (int i = tid; i < 128 * DIM; i += 128) {
            int r = i >> 6, c = i & 63;
            if (base + r < N) hout[gb + i] = rows[r * 65 + c];
        }
    }

    // threads 0..63: segmented pre-BN pool sums + block total sum
    // threads 64..127: BN sum of squares  (padded rows are zero)
    if (tid < 64) {
        int j = tid;
        int cur = bats[0];
        float acc = 0.0f;
        float tot = 0.0f;
        for (int r = 0; r < 128; r++) {
            int g = bats[r];
            float v = rows[r * 65 + j];
            if (g != cur) {
                atomicAdd(&pool[cur * DIM + j], acc);
                acc = 0.0f;
                cur = g;
            }
            acc += v;
            tot += v;
        }
        atomicAdd(&pool[cur * DIM + j], acc);
        atomicAdd(&totsum[j], tot);
    } else {
        int j = tid - 64;
        float s = 0.0f;
        for (int r = 0; r < 128; r++) {
            float v = rows[r * 65 + j];
            s += v * v;
        }
        atomicAdd(&stats[j], s);
    }
}

// ---------------- output write (BN folded, scale/shift inline) -------------
__global__ void outwrite_kernel(const float* __restrict__ ps,
                                const float* __restrict__ gamma,
                                const float* __restrict__ beta,
                                float* __restrict__ out, int col_off,
                                float invN, int G) {
    int idx = blockIdx.x * blockDim.x + threadIdx.x;
    if (idx >= G * DIM) return;
    int g = idx >> 6, j = idx & 63;
    float mean = __ldg(ps + MAX_G * DIM + DIM + j) * invN;
    float var  = __ldg(ps + MAX_G * DIM + j) * invN - mean * mean;
    float sc   = __ldg(gamma + j) * rsqrtf(var + BN_EPS);
    float sh   = __ldg(beta + j) - mean * sc;
    out[g * 128 + col_off + j] = sc * ps[idx] + (float)__ldg(&CNTP[g]) * sh;
}

// ---------------------------------------------------------------------------
extern "C" void kernel_launch(void* const* d_in, const int* in_sizes, int n_in,
                              void* d_out, int out_size) {
    const float* x       = (const float*)d_in[0];
    const float* W1_0    = (const float*)d_in[1];
    const float* b1_0    = (const float*)d_in[2];
    const float* W2_0    = (const float*)d_in[3];
    const float* b2_0    = (const float*)d_in[4];
    const float* gamma_0 = (const float*)d_in[5];
    const float* beta_0  = (const float*)d_in[6];
    const float* W1_1    = (const float*)d_in[7];
    const float* b1_1    = (const float*)d_in[8];
    const float* W2_1    = (const float*)d_in[9];
    const float* b2_1    = (const float*)d_in[10];
    const float* gamma_1 = (const float*)d_in[11];
    const float* beta_1  = (const float*)d_in[12];
    const int*   ei      = (const int*)d_in[13];
    const int*   batch   = (const int*)d_in[14];

    int N = in_sizes[0] / DIM;
    int E = in_sizes[13] / 2;
    int G = out_size / 128;
    float* out = (float*)d_out;

    void *zero_p, *h0_p, *hin_p;
    cudaGetSymbolAddress(&zero_p, g_zeroed);
    cudaGetSymbolAddress(&h0_p, g_h0);
    cudaGetSymbolAddress(&hin_p, g_hin);

    float* ps0 = (float*)zero_p;
    float* ps1 = ps0 + PS_FLOATS;

    int work = (E > N) ? E : N;
    int fill_blocks = (work + 255) / 256;
    int agg_blocks  = (N + 7) / 8;
    int mlp_blocks  = (N + 127) / 128;
    int ow_blocks   = (G * DIM + 255) / 256;
    float invN = 1.0f / (float)N;

    // ---- scratch zero + weights into constant memory (D2D) ----
    cudaMemsetAsync(zero_p, 0, sizeof(g_zeroed));
    cudaMemcpyToSymbolAsync(c_W, W1_0, 16384, 0,     cudaMemcpyDeviceToDevice);
    cudaMemcpyToSymbolAsync(c_W, W2_0, 16384, 16384, cudaMemcpyDeviceToDevice);
    cudaMemcpyToSymbolAsync(c_W, W1_1, 16384, 32768, cudaMemcpyDeviceToDevice);
    cudaMemcpyToSymbolAsync(c_W, W2_1, 16384, 49152, cudaMemcpyDeviceToDevice);
    fill_cnt_kernel<<<fill_blocks, 256>>>(ei, batch, E, N);

    // ---------------- layer 0 ----------------
    aggregate_kernel<false><<<agg_blocks, 128>>>(
        x, (float*)hin_p, nullptr, nullptr, nullptr, invN, N);
    mlp_kernel<0, true><<<mlp_blocks, 128>>>(
        (const float*)hin_p, b1_0, b2_0, batch, (float*)h0_p, ps0, N);
    outwrite_kernel<<<ow_blocks, 256>>>(ps0, gamma_0, beta_0, out, 0, invN, G);

    // ---------------- layer 1 (reads raw h0, folds BN0 inline) -------------
    aggregate_kernel<true><<<agg_blocks, 128>>>(
        (const float*)h0_p, (float*)hin_p, ps0, gamma_0, beta_0, invN, N);
    mlp_kernel<1, false><<<mlp_blocks, 128>>>(
        (const float*)hin_p, b1_1, b2_1, batch, nullptr, ps1, N);
    outwrite_kernel<<<ow_blocks, 256>>>(ps1, gamma_1, beta_1, out, 64, invN, G);
}

// round 10
// speedup vs baseline: 1.1948x; 1.1948x over previous
#include <cuda_runtime.h>

// ---------------------------------------------------------------------------
// GIN encoder. Bucketed-CSR pipeline + algebraic BN fold, 7 launches:
//   memset -> fill -> agg0 -> mlp0 -> agg1(+outwrite0 tail) -> mlp1 -> ow1
//   out[g] = scale * poolsum_preBN[g] + cnt[g] * shift
//   hin1   = sc0*(h0[n] + sum h0[src]) + (1+deg)*sh0     (x0 never stored)
// MLP weights staged through a single DYNAMIC shared buffer (W1 then W2):
// smem ~50KB (opt-in via cudaFuncSetAttribute) -> 4 blocks/SM.
// ---------------------------------------------------------------------------

#define MAX_N 100000
#define MAX_G 1024
#define DIM 64
#define BN_EPS 1e-5f
#define SLOTS 64

// per-layer reduction buffer: pool[MAX_G*DIM] | sumsq[DIM] | totsum[DIM]
#define PS_FLOATS (MAX_G * DIM + 2 * DIM)

// single zeroed scratch region: ps0 | ps1 | deg[MAX_N] | cnt[MAX_G]
__device__ __align__(16) unsigned int g_zeroed[2 * PS_FLOATS + MAX_N + MAX_G];
#define DEGP ((int*)g_zeroed + 2 * PS_FLOATS)
#define CNTP (DEGP + MAX_N)

__device__ __align__(16) float g_h0 [MAX_N * DIM];   // layer-0 pre-BN h
__device__ __align__(16) float g_hin[MAX_N * DIM];   // MLP inputs
__device__ __align__(16) int g_srcidx[MAX_N * SLOTS];

// dynamic smem layout for mlp_kernel: Ws[4096] | rows[128*65] | bats[128]
#define MLP_SMEM_FLOATS (4096 + 128 * 65 + 128)
#define MLP_SMEM_BYTES  (MLP_SMEM_FLOATS * 4)

// ---------------- packed f32x2 + tanh helpers (sm_100+) --------------------
static __device__ __forceinline__ unsigned long long ffma2(
    unsigned long long a, unsigned long long b, unsigned long long c) {
    unsigned long long d;
    asm("fma.rn.f32x2 %0, %1, %2, %3;" : "=l"(d) : "l"(a), "l"(b), "l"(c));
    return d;
}
static __device__ __forceinline__ unsigned long long pack2(float x, float y) {
    unsigned long long r;
    asm("mov.b64 %0, {%1, %2};" : "=l"(r) : "f"(x), "f"(y));
    return r;
}
static __device__ __forceinline__ float2 unpack2(unsigned long long v) {
    float2 f;
    asm("mov.b64 {%0, %1}, %2;" : "=f"(f.x), "=f"(f.y) : "l"(v));
    return f;
}
static __device__ __forceinline__ float tanha(float x) {
    float y;
    asm("tanh.approx.f32 %0, %1;" : "=f"(y) : "f"(x));
    return y;
}

// ---------------- bucket fill + graph counts -------------------------------
__global__ void fill_cnt_kernel(const int* __restrict__ ei,
                                const int* __restrict__ batch, int E, int N) {
    int t = blockIdx.x * blockDim.x + threadIdx.x;
    if (t < E) {
        int s = __ldg(ei + t);
        int d = __ldg(ei + E + t);
        int pos = atomicAdd(&DEGP[d], 1);
        if (pos < SLOTS) g_srcidx[d * SLOTS + pos] = s;
    }
    if (t < N) atomicAdd(&CNTP[__ldg(batch + t)], 1);
}

// ---------------- aggregation (gather, no atomics) -------------------------
// 16 lanes per node (float4 columns), 8 nodes per 128-thread block.
// AFFINE: folds previous layer's BN inline; tail blocks beyond aggBlocks do
// the previous layer's output write (outwrite col 0..63).
template <bool AFFINE>
__global__ __launch_bounds__(128) void aggregate_kernel(
    const float* __restrict__ x, float* __restrict__ hout,
    const float* __restrict__ psPrev,
    const float* __restrict__ gamma, const float* __restrict__ beta,
    float* __restrict__ out, float invN, int N, int G, int aggBlocks) {
    if (AFFINE && (int)blockIdx.x >= aggBlocks) {
        // outwrite duty for the PREVIOUS layer (col_off = 0)
        int idx = ((int)blockIdx.x - aggBlocks) * 128 + threadIdx.x;
        if (idx < G * DIM) {
            int g = idx >> 6, j = idx & 63;
            float mean = __ldg(psPrev + MAX_G * DIM + DIM + j) * invN;
            float var  = __ldg(psPrev + MAX_G * DIM + j) * invN - mean * mean;
            float sc   = __ldg(gamma + j) * rsqrtf(var + BN_EPS);
            float sh   = __ldg(beta + j) - mean * sc;
            out[g * 128 + j] =
                sc * psPrev[idx] + (float)__ldg(&CNTP[g]) * sh;
        }
        return;
    }
    int node = blockIdx.x * 8 + (threadIdx.x >> 4);
    int c = threadIdx.x & 15;
    if (node >= N) return;
    int deg = __ldg(&DEGP[node]);
    const float4* x4 = reinterpret_cast<const float4*>(x);
    const int4* idx4 = reinterpret_cast<const int4*>(g_srcidx + node * SLOTS);
    float4 acc = x4[node * 16 + c];
    int e = 0;
    for (; e + 4 <= deg; e += 4) {
        int4 s = __ldg(&idx4[e >> 2]);
        float4 v0 = x4[s.x * 16 + c];
        float4 v1 = x4[s.y * 16 + c];
        float4 v2 = x4[s.z * 16 + c];
        float4 v3 = x4[s.w * 16 + c];
        acc.x += (v0.x + v1.x) + (v2.x + v3.x);
        acc.y += (v0.y + v1.y) + (v2.y + v3.y);
        acc.z += (v0.z + v1.z) + (v2.z + v3.z);
        acc.w += (v0.w + v1.w) + (v2.w + v3.w);
    }
    for (; e < deg; e++) {
        int s = __ldg(g_srcidx + node * SLOTS + e);
        float4 v0 = x4[s * 16 + c];
        acc.x += v0.x;
        acc.y += v0.y;
        acc.z += v0.z;
        acc.w += v0.w;
    }
    if (AFFINE) {
        const float4* ss4 = reinterpret_cast<const float4*>(psPrev + MAX_G * DIM);
        const float4* ts4 = reinterpret_cast<const float4*>(psPrev + MAX_G * DIM + DIM);
        float4 ssq = __ldg(&ss4[c]);
        float4 tot = __ldg(&ts4[c]);
        float4 gm = __ldg(&reinterpret_cast<const float4*>(gamma)[c]);
        float4 bt = __ldg(&reinterpret_cast<const float4*>(beta)[c]);
        float f = (float)(1 + deg);
        float mx = tot.x * invN, my = tot.y * invN,
              mz = tot.z * invN, mw = tot.w * invN;
        float scx = gm.x * rsqrtf(ssq.x * invN - mx * mx + BN_EPS);
        float scy = gm.y * rsqrtf(ssq.y * invN - my * my + BN_EPS);
        float scz = gm.z * rsqrtf(ssq.z * invN - mz * mz + BN_EPS);
        float scw = gm.w * rsqrtf(ssq.w * invN - mw * mw + BN_EPS);
        acc.x = acc.x * scx + f * (bt.x - mx * scx);
        acc.y = acc.y * scy + f * (bt.y - my * scy);
        acc.z = acc.z * scz + f * (bt.z - mz * scz);
        acc.w = acc.w * scw + f * (bt.w - mw * scw);
    }
    reinterpret_cast<float4*>(hout)[node * 16 + c] = acc;
}

// ---------------- MLP stage (shared weights, f32x2 FMA, MUFU tanh) ---------
static __device__ __forceinline__ void mlp_stage(float* row,
                                                 const float* Ws,
                                                 const float* __restrict__ bias) {
    unsigned long long acc[32];
    const ulonglong2* bp = reinterpret_cast<const ulonglong2*>(bias);
#pragma unroll
    for (int j = 0; j < 16; j++) {
        ulonglong2 b = __ldg(&bp[j]);
        acc[2 * j + 0] = b.x;
        acc[2 * j + 1] = b.y;
    }

    for (int k = 0; k < DIM; k++) {
        float xk = row[k];
        unsigned long long xx = pack2(xk, xk);
        const ulonglong2* Wp =
            reinterpret_cast<const ulonglong2*>(Ws + (k << 6));
#pragma unroll
        for (int j = 0; j < 16; j++) {
            ulonglong2 w = Wp[j];
            acc[2 * j + 0] = ffma2(xx, w.x, acc[2 * j + 0]);
            acc[2 * j + 1] = ffma2(xx, w.y, acc[2 * j + 1]);
        }
    }
#pragma unroll
    for (int j = 0; j < 32; j++) {
        float2 v = unpack2(acc[j]);
        row[2 * j + 0] = tanha(v.x);
        row[2 * j + 1] = tanha(v.y);
    }
}

// ---------------- MLP + BN stats + pre-BN pool sums ------------------------
// Single staged weight buffer in DYNAMIC smem: ~50KB -> 4 blocks/SM.
template <bool WRITE_H>
__global__ __launch_bounds__(128) void mlp_kernel(
    const float* __restrict__ hin,
    const float* __restrict__ W1, const float* __restrict__ b1,
    const float* __restrict__ W2, const float* __restrict__ b2,
    const int* __restrict__ batch, float* __restrict__ hout,
    float* __restrict__ ps, int N) {
    extern __shared__ float sm[];
    float* Ws   = sm;                       // 4096
    float* rows = sm + 4096;                // 128 * 65
    int*   bats = (int*)(sm + 4096 + 128 * 65);  // 128

    float* pool   = ps;
    float* stats  = ps + MAX_G * DIM;
    float* totsum = ps + MAX_G * DIM + DIM;

    int tid  = threadIdx.x;
    int base = blockIdx.x * 128;
    int node = base + tid;

    for (int i = tid; i < 4096; i += 128) Ws[i] = __ldg(W1 + i);
    bats[tid] = __ldg(batch + (node < N ? node : N - 1));

    float* myrow = rows + tid * 65;
    if (node < N) {
        const float4* h4 = reinterpret_cast<const float4*>(hin);
#pragma unroll
        for (int c = 0; c < 16; c++) {
            float4 v = h4[node * 16 + c];
            myrow[4 * c + 0] = v.x;
            myrow[4 * c + 1] = v.y;
            myrow[4 * c + 2] = v.z;
            myrow[4 * c + 3] = v.w;
        }
    } else {
#pragma unroll
        for (int c = 0; c < DIM; c++) myrow[c] = 0.0f;
    }
    __syncthreads();                       // W1 + rows ready

    if (node < N) mlp_stage(myrow, Ws, b1);
    __syncthreads();                       // all done reading W1

    for (int i = tid; i < 4096; i += 128) Ws[i] = __ldg(W2 + i);
    __syncthreads();                       // W2 ready

    if (node < N) mlp_stage(myrow, Ws, b2);
    __syncthreads();                       // rows final for phase 3

    if (WRITE_H) {
        int gb = base * DIM;
        for (int i = tid; i < 128 * DIM; i += 128) {
            int r = i >> 6, c = i & 63;
            if (base + r < N) hout[gb + i] = rows[r * 65 + c];
        }
    }

    // threads 0..63: segmented pre-BN pool sums + block total sum
    // threads 64..127: BN sum of squares  (padded rows are zero)
    if (tid < 64) {
        int j = tid;
        int cur = bats[0];
        float acc = 0.0f;
        float tot = 0.0f;
        for (int r = 0; r < 128; r++) {
            int g = bats[r];
            float v = rows[r * 65 + j];
            if (g != cur) {
                atomicAdd(&pool[cur * DIM + j], acc);
                acc = 0.0f;
                cur = g;
            }
            acc += v;
            tot += v;
        }
        atomicAdd(&pool[cur * DIM + j], acc);
        atomicAdd(&totsum[j], tot);
    } else {
        int j = tid - 64;
        float s = 0.0f;
        for (int r = 0; r < 128; r++) {
            float v = rows[r * 65 + j];
            s += v * v;
        }
        atomicAdd(&stats[j], s);
    }
}

// ---------------- output write (BN folded, scale/shift inline) -------------
__global__ void outwrite_kernel(const float* __restrict__ ps,
                                const float* __restrict__ gamma,
                                const float* __restrict__ beta,
                                float* __restrict__ out, int col_off,
                                float invN, int G) {
    int idx = blockIdx.x * blockDim.x + threadIdx.x;
    if (idx >= G * DIM) return;
    int g = idx >> 6, j = idx & 63;
    float mean = __ldg(ps + MAX_G * DIM + DIM + j) * invN;
    float var  = __ldg(ps + MAX_G * DIM + j) * invN - mean * mean;
    float sc   = __ldg(gamma + j) * rsqrtf(var + BN_EPS);
    float sh   = __ldg(beta + j) - mean * sc;
    out[g * 128 + col_off + j] = sc * ps[idx] + (float)__ldg(&CNTP[g]) * sh;
}

// ---------------------------------------------------------------------------
extern "C" void kernel_launch(void* const* d_in, const int* in_sizes, int n_in,
                              void* d_out, int out_size) {
    const float* x       = (const float*)d_in[0];
    const float* W1_0    = (const float*)d_in[1];
    const float* b1_0    = (const float*)d_in[2];
    const float* W2_0    = (const float*)d_in[3];
    const float* b2_0    = (const float*)d_in[4];
    const float* gamma_0 = (const float*)d_in[5];
    const float* beta_0  = (const float*)d_in[6];
    const float* W1_1    = (const float*)d_in[7];
    const float* b1_1    = (const float*)d_in[8];
    const float* W2_1    = (const float*)d_in[9];
    const float* b2_1    = (const float*)d_in[10];
    const float* gamma_1 = (const float*)d_in[11];
    const float* beta_1  = (const float*)d_in[12];
    const int*   ei      = (const int*)d_in[13];
    const int*   batch   = (const int*)d_in[14];

    int N = in_sizes[0] / DIM;
    int E = in_sizes[13] / 2;
    int G = out_size / 128;
    float* out = (float*)d_out;

    void *zero_p, *h0_p, *hin_p;
    cudaGetSymbolAddress(&zero_p, g_zeroed);
    cudaGetSymbolAddress(&h0_p, g_h0);
    cudaGetSymbolAddress(&hin_p, g_hin);

    float* ps0 = (float*)zero_p;
    float* ps1 = ps0 + PS_FLOATS;

    cudaFuncSetAttribute(mlp_kernel<true>,
                         cudaFuncAttributeMaxDynamicSharedMemorySize,
                         MLP_SMEM_BYTES);
    cudaFuncSetAttribute(mlp_kernel<false>,
                         cudaFuncAttributeMaxDynamicSharedMemorySize,
                         MLP_SMEM_BYTES);

    int work = (E > N) ? E : N;
    int fill_blocks = (work + 255) / 256;
    int agg_blocks  = (N + 7) / 8;
    int ow_tail     = (G * DIM + 127) / 128;
    int mlp_blocks  = (N + 127) / 128;
    int ow_blocks   = (G * DIM + 255) / 256;
    float invN = 1.0f / (float)N;

    // ---- one memset for all zeroed scratch ----
    cudaMemsetAsync(zero_p, 0, sizeof(g_zeroed));
    fill_cnt_kernel<<<fill_blocks, 256>>>(ei, batch, E, N);

    // ---------------- layer 0 ----------------
    aggregate_kernel<false><<<agg_blocks, 128>>>(
        x, (float*)hin_p, nullptr, nullptr, nullptr, nullptr, invN, N, G,
        agg_blocks);
    mlp_kernel<true><<<mlp_blocks, 128, MLP_SMEM_BYTES>>>(
        (const float*)hin_p, W1_0, b1_0, W2_0, b2_0, batch,
        (float*)h0_p, ps0, N);

    // ---------------- layer 1 (agg folds BN0 inline; tail = outwrite0) -----
    aggregate_kernel<true><<<agg_blocks + ow_tail, 128>>>(
        (const float*)h0_p, (float*)hin_p, ps0, gamma_0, beta_0, out,
        invN, N, G, agg_blocks);
    mlp_kernel<false><<<mlp_blocks, 128, MLP_SMEM_BYTES>>>(
        (const float*)hin_p, W1_1, b1_1, W2_1, b2_1, batch,
        nullptr, ps1, N);
    outwrite_kernel<<<ow_blocks, 256>>>(ps1, gamma_1, beta_1, out, 64, invN, G);
}

// round 11
// speedup vs baseline: 1.2369x; 1.0352x over previous
#include <cuda_runtime.h>
#include <cuda_fp16.h>

// ---------------------------------------------------------------------------
// GIN encoder. Bucketed-CSR pipeline + algebraic BN fold, 7 launches:
//   memset -> fill(+x->fp16 cvt) -> agg0 -> mlp0 -> agg1(+outwrite0 tail)
//   -> mlp1 -> ow1
// Activations stored fp16 (gather bandwidth halved); all math fp32.
//   out[g] = scale * poolsum_preBN[g] + cnt[g] * shift
//   hin1   = sc0*(h0[n] + sum h0[src]) + (1+deg)*sh0     (x0 never stored)
// ---------------------------------------------------------------------------

#define MAX_N 100000
#define MAX_G 1024
#define DIM 64
#define BN_EPS 1e-5f
#define SLOTS 64

// per-layer reduction buffer: pool[MAX_G*DIM] | sumsq[DIM] | totsum[DIM]
#define PS_FLOATS (MAX_G * DIM + 2 * DIM)

// single zeroed scratch region: ps0 | ps1 | deg[MAX_N] | cnt[MAX_G]
__device__ __align__(16) unsigned int g_zeroed[2 * PS_FLOATS + MAX_N + MAX_G];
#define DEGP ((int*)g_zeroed + 2 * PS_FLOATS)
#define CNTP (DEGP + MAX_N)

__device__ __align__(16) __half g_xh [MAX_N * DIM];  // fp16 copy of x
__device__ __align__(16) __half g_h0h[MAX_N * DIM];  // layer-0 pre-BN h, fp16
__device__ __align__(16) __half g_hin[MAX_N * DIM];  // MLP inputs, fp16
__device__ __align__(16) int g_srcidx[MAX_N * SLOTS];

// dynamic smem layout for mlp_kernel: Ws[4096] | rows[128*65] | bats[128]
#define MLP_SMEM_FLOATS (4096 + 128 * 65 + 128)
#define MLP_SMEM_BYTES  (MLP_SMEM_FLOATS * 4)

// ---------------- helpers --------------------------------------------------
static __device__ __forceinline__ unsigned long long ffma2(
    unsigned long long a, unsigned long long b, unsigned long long c) {
    unsigned long long d;
    asm("fma.rn.f32x2 %0, %1, %2, %3;" : "=l"(d) : "l"(a), "l"(b), "l"(c));
    return d;
}
static __device__ __forceinline__ unsigned long long pack2(float x, float y) {
    unsigned long long r;
    asm("mov.b64 %0, {%1, %2};" : "=l"(r) : "f"(x), "f"(y));
    return r;
}
static __device__ __forceinline__ float2 unpack2(unsigned long long v) {
    float2 f;
    asm("mov.b64 {%0, %1}, %2;" : "=f"(f.x), "=f"(f.y) : "l"(v));
    return f;
}
static __device__ __forceinline__ float tanha(float x) {
    float y;
    asm("tanh.approx.f32 %0, %1;" : "=f"(y) : "f"(x));
    return y;
}
static __device__ __forceinline__ float4 h4_to_f4(uint2 v) {
    __half2 a = *reinterpret_cast<__half2*>(&v.x);
    __half2 b = *reinterpret_cast<__half2*>(&v.y);
    float2 fa = __half22float2(a);
    float2 fb = __half22float2(b);
    return make_float4(fa.x, fa.y, fb.x, fb.y);
}
static __device__ __forceinline__ uint2 f4_to_h4(float4 f) {
    __half2 a = __float22half2_rn(make_float2(f.x, f.y));
    __half2 b = __float22half2_rn(make_float2(f.z, f.w));
    uint2 v;
    v.x = *reinterpret_cast<unsigned int*>(&a);
    v.y = *reinterpret_cast<unsigned int*>(&b);
    return v;
}

// ---------------- bucket fill + graph counts + x->fp16 convert -------------
__global__ void fill_cnt_cvt_kernel(const int* __restrict__ ei,
                                    const int* __restrict__ batch,
                                    const float* __restrict__ x,
                                    int E, int N, int CV) {
    int t = blockIdx.x * blockDim.x + threadIdx.x;
    if (t < E) {
        int s = __ldg(ei + t);
        int d = __ldg(ei + E + t);
        int pos = atomicAdd(&DEGP[d], 1);
        if (pos < SLOTS) g_srcidx[d * SLOTS + pos] = s;
    }
    if (t < N) atomicAdd(&CNTP[__ldg(batch + t)], 1);
    if (t < CV) {
        float4 v = __ldg(&reinterpret_cast<const float4*>(x)[t]);
        reinterpret_cast<uint2*>(g_xh)[t] = f4_to_h4(v);
    }
}

// ---------------- aggregation (fp16 gather, fp32 accumulate) ---------------
// 16 lanes per node (uint2 = 4 halves per lane), 8 nodes per 128-thread block.
// AFFINE: folds previous layer's BN inline; tail blocks do outwrite0.
template <bool AFFINE>
__global__ __launch_bounds__(128) void aggregate_kernel(
    const __half* __restrict__ xh, __half* __restrict__ hout,
    const float* __restrict__ psPrev,
    const float* __restrict__ gamma, const float* __restrict__ beta,
    float* __restrict__ out, float invN, int N, int G, int aggBlocks) {
    if (AFFINE && (int)blockIdx.x >= aggBlocks) {
        // outwrite duty for the PREVIOUS layer (col_off = 0)
        int idx = ((int)blockIdx.x - aggBlocks) * 128 + threadIdx.x;
        if (idx < G * DIM) {
            int g = idx >> 6, j = idx & 63;
            float mean = __ldg(psPrev + MAX_G * DIM + DIM + j) * invN;
            float var  = __ldg(psPrev + MAX_G * DIM + j) * invN - mean * mean;
            float sc   = __ldg(gamma + j) * rsqrtf(var + BN_EPS);
            float sh   = __ldg(beta + j) - mean * sc;
            out[g * 128 + j] =
                sc * psPrev[idx] + (float)__ldg(&CNTP[g]) * sh;
        }
        return;
    }
    int node = blockIdx.x * 8 + (threadIdx.x >> 4);
    int c = threadIdx.x & 15;
    if (node >= N) return;
    int deg = __ldg(&DEGP[node]);
    const uint2* x2 = reinterpret_cast<const uint2*>(xh);
    const int4* idx4 = reinterpret_cast<const int4*>(g_srcidx + node * SLOTS);
    float4 acc = h4_to_f4(__ldg(&x2[node * 16 + c]));
    int e = 0;
    for (; e + 4 <= deg; e += 4) {
        int4 s = __ldg(&idx4[e >> 2]);
        float4 v0 = h4_to_f4(__ldg(&x2[s.x * 16 + c]));
        float4 v1 = h4_to_f4(__ldg(&x2[s.y * 16 + c]));
        float4 v2 = h4_to_f4(__ldg(&x2[s.z * 16 + c]));
        float4 v3 = h4_to_f4(__ldg(&x2[s.w * 16 + c]));
        acc.x += (v0.x + v1.x) + (v2.x + v3.x);
        acc.y += (v0.y + v1.y) + (v2.y + v3.y);
        acc.z += (v0.z + v1.z) + (v2.z + v3.z);
        acc.w += (v0.w + v1.w) + (v2.w + v3.w);
    }
    for (; e < deg; e++) {
        int s = __ldg(g_srcidx + node * SLOTS + e);
        float4 v0 = h4_to_f4(__ldg(&x2[s * 16 + c]));
        acc.x += v0.x;
        acc.y += v0.y;
        acc.z += v0.z;
        acc.w += v0.w;
    }
    if (AFFINE) {
        const float4* ss4 = reinterpret_cast<const float4*>(psPrev + MAX_G * DIM);
        const float4* ts4 = reinterpret_cast<const float4*>(psPrev + MAX_G * DIM + DIM);
        float4 ssq = __ldg(&ss4[c]);
        float4 tot = __ldg(&ts4[c]);
        float4 gm = __ldg(&reinterpret_cast<const float4*>(gamma)[c]);
        float4 bt = __ldg(&reinterpret_cast<const float4*>(beta)[c]);
        float f = (float)(1 + deg);
        float mx = tot.x * invN, my = tot.y * invN,
              mz = tot.z * invN, mw = tot.w * invN;
        float scx = gm.x * rsqrtf(ssq.x * invN - mx * mx + BN_EPS);
        float scy = gm.y * rsqrtf(ssq.y * invN - my * my + BN_EPS);
        float scz = gm.z * rsqrtf(ssq.z * invN - mz * mz + BN_EPS);
        float scw = gm.w * rsqrtf(ssq.w * invN - mw * mw + BN_EPS);
        acc.x = acc.x * scx + f * (bt.x - mx * scx);
        acc.y = acc.y * scy + f * (bt.y - my * scy);
        acc.z = acc.z * scz + f * (bt.z - mz * scz);
        acc.w = acc.w * scw + f * (bt.w - mw * scw);
    }
    reinterpret_cast<uint2*>(hout)[node * 16 + c] = f4_to_h4(acc);
}

// ---------------- MLP stage (shared weights, f32x2 FMA, MUFU tanh) ---------
static __device__ __forceinline__ void mlp_stage(float* row,
                                                 const float* Ws,
                                                 const float* __restrict__ bias) {
    unsigned long long acc[32];
    const ulonglong2* bp = reinterpret_cast<const ulonglong2*>(bias);
#pragma unroll
    for (int j = 0; j < 16; j++) {
        ulonglong2 b = __ldg(&bp[j]);
        acc[2 * j + 0] = b.x;
        acc[2 * j + 1] = b.y;
    }

#pragma unroll 4
    for (int k = 0; k < DIM; k++) {
        float xk = row[k];
        unsigned long long xx = pack2(xk, xk);
        const ulonglong2* Wp =
            reinterpret_cast<const ulonglong2*>(Ws + (k << 6));
#pragma unroll
        for (int j = 0; j < 16; j++) {
            ulonglong2 w = Wp[j];
            acc[2 * j + 0] = ffma2(xx, w.x, acc[2 * j + 0]);
            acc[2 * j + 1] = ffma2(xx, w.y, acc[2 * j + 1]);
        }
    }
#pragma unroll
    for (int j = 0; j < 32; j++) {
        float2 v = unpack2(acc[j]);
        row[2 * j + 0] = tanha(v.x);
        row[2 * j + 1] = tanha(v.y);
    }
}

// ---------------- MLP + BN stats + pre-BN pool sums ------------------------
// Single staged weight buffer in DYNAMIC smem: ~50KB -> 4 blocks/SM.
template <bool WRITE_H>
__global__ __launch_bounds__(128) void mlp_kernel(
    const __half* __restrict__ hin,
    const float* __restrict__ W1, const float* __restrict__ b1,
    const float* __restrict__ W2, const float* __restrict__ b2,
    const int* __restrict__ batch, __half* __restrict__ hout,
    float* __restrict__ ps, int N) {
    extern __shared__ float sm[];
    float* Ws   = sm;                       // 4096
    float* rows = sm + 4096;                // 128 * 65
    int*   bats = (int*)(sm + 4096 + 128 * 65);  // 128

    float* pool   = ps;
    float* stats  = ps + MAX_G * DIM;
    float* totsum = ps + MAX_G * DIM + DIM;

    int tid  = threadIdx.x;
    int base = blockIdx.x * 128;
    int node = base + tid;

    for (int i = tid; i < 4096; i += 128) Ws[i] = __ldg(W1 + i);
    bats[tid] = __ldg(batch + (node < N ? node : N - 1));

    float* myrow = rows + tid * 65;
    if (node < N) {
        const uint2* h2 = reinterpret_cast<const uint2*>(hin);
#pragma unroll
        for (int c = 0; c < 16; c++) {
            float4 v = h4_to_f4(__ldg(&h2[node * 16 + c]));
            myrow[4 * c + 0] = v.x;
            myrow[4 * c + 1] = v.y;
            myrow[4 * c + 2] = v.z;
            myrow[4 * c + 3] = v.w;
        }
    } else {
#pragma unroll
        for (int c = 0; c < DIM; c++) myrow[c] = 0.0f;
    }
    __syncthreads();                       // W1 + rows ready

    if (node < N) mlp_stage(myrow, Ws, b1);
    __syncthreads();                       // all done reading W1

    for (int i = tid; i < 4096; i += 128) Ws[i] = __ldg(W2 + i);
    __syncthreads();                       // W2 ready

    if (node < N) mlp_stage(myrow, Ws, b2);
    __syncthreads();                       // rows final for phase 3

    if (WRITE_H) {
        __half2* ho = reinterpret_cast<__half2*>(hout);
        for (int i = tid; i < 128 * 32; i += 128) {
            int r = i >> 5, c = (i & 31) << 1;
            if (base + r < N) {
                ho[(base + r) * 32 + (i & 31)] = __float22half2_rn(
                    make_float2(rows[r * 65 + c], rows[r * 65 + c + 1]));
            }
        }
    }

    // threads 0..63: segmented pre-BN pool sums + block total sum
    // threads 64..127: BN sum of squares  (padded rows are zero)
    if (tid < 64) {
        int j = tid;
        int cur = bats[0];
        float acc = 0.0f;
        float tot = 0.0f;
        for (int r = 0; r < 128; r++) {
            int g = bats[r];
            float v = rows[r * 65 + j];
            if (g != cur) {
                atomicAdd(&pool[cur * DIM + j], acc);
                acc = 0.0f;
                cur = g;
            }
            acc += v;
            tot += v;
        }
        atomicAdd(&pool[cur * DIM + j], acc);
        atomicAdd(&totsum[j], tot);
    } else {
        int j = tid - 64;
        float s = 0.0f;
        for (int r = 0; r < 128; r++) {
            float v = rows[r * 65 + j];
            s += v * v;
        }
        atomicAdd(&stats[j], s);
    }
}

// ---------------- output write (BN folded, scale/shift inline) -------------
__global__ void outwrite_kernel(const float* __restrict__ ps,
                                const float* __restrict__ gamma,
                                const float* __restrict__ beta,
                                float* __restrict__ out, int col_off,
                                float invN, int G) {
    int idx = blockIdx.x * blockDim.x + threadIdx.x;
    if (idx >= G * DIM) return;
    int g = idx >> 6, j = idx & 63;
    float mean = __ldg(ps + MAX_G * DIM + DIM + j) * invN;
    float var  = __ldg(ps + MAX_G * DIM + j) * invN - mean * mean;
    float sc   = __ldg(gamma + j) * rsqrtf(var + BN_EPS);
    float sh   = __ldg(beta + j) - mean * sc;
    out[g * 128 + col_off + j] = sc * ps[idx] + (float)__ldg(&CNTP[g]) * sh;
}

// ---------------------------------------------------------------------------
extern "C" void kernel_launch(void* const* d_in, const int* in_sizes, int n_in,
                              void* d_out, int out_size) {
    const float* x       = (const float*)d_in[0];
    const float* W1_0    = (const float*)d_in[1];
    const float* b1_0    = (const float*)d_in[2];
    const float* W2_0    = (const float*)d_in[3];
    const float* b2_0    = (const float*)d_in[4];
    const float* gamma_0 = (const float*)d_in[5];
    const float* beta_0  = (const float*)d_in[6];
    const float* W1_1    = (const float*)d_in[7];
    const float* b1_1    = (const float*)d_in[8];
    const float* W2_1    = (const float*)d_in[9];
    const float* b2_1    = (const float*)d_in[10];
    const float* gamma_1 = (const float*)d_in[11];
    const float* beta_1  = (const float*)d_in[12];
    const int*   ei      = (const int*)d_in[13];
    const int*   batch   = (const int*)d_in[14];

    int N = in_sizes[0] / DIM;
    int E = in_sizes[13] / 2;
    int G = out_size / 128;
    float* out = (float*)d_out;

    void *zero_p, *xh_p, *h0_p, *hin_p;
    cudaGetSymbolAddress(&zero_p, g_zeroed);
    cudaGetSymbolAddress(&xh_p, g_xh);
    cudaGetSymbolAddress(&h0_p, g_h0h);
    cudaGetSymbolAddress(&hin_p, g_hin);

    float* ps0 = (float*)zero_p;
    float* ps1 = ps0 + PS_FLOATS;

    cudaFuncSetAttribute(mlp_kernel<true>,
                         cudaFuncAttributeMaxDynamicSharedMemorySize,
                         MLP_SMEM_BYTES);
    cudaFuncSetAttribute(mlp_kernel<false>,
                         cudaFuncAttributeMaxDynamicSharedMemorySize,
                         MLP_SMEM_BYTES);

    int CV = N * DIM / 4;   // float4 conversion threads
    int work = E;
    if (N > work) work = N;
    if (CV > work) work = CV;
    int fill_blocks = (work + 255) / 256;
    int agg_blocks  = (N + 7) / 8;
    int ow_tail     = (G * DIM + 127) / 128;
    int mlp_blocks  = (N + 127) / 128;
    int ow_blocks   = (G * DIM + 255) / 256;
    float invN = 1.0f / (float)N;

    // ---- one memset for all zeroed scratch ----
    cudaMemsetAsync(zero_p, 0, sizeof(g_zeroed));
    fill_cnt_cvt_kernel<<<fill_blocks, 256>>>(ei, batch, x, E, N, CV);

    // ---------------- layer 0 ----------------
    aggregate_kernel<false><<<agg_blocks, 128>>>(
        (const __half*)xh_p, (__half*)hin_p, nullptr, nullptr, nullptr,
        nullptr, invN, N, G, agg_blocks);
    mlp_kernel<true><<<mlp_blocks, 128, MLP_SMEM_BYTES>>>(
        (const __half*)hin_p, W1_0, b1_0, W2_0, b2_0, batch,
        (__half*)h0_p, ps0, N);

    // ---------------- layer 1 (agg folds BN0 inline; tail = outwrite0) -----
    aggregate_kernel<true><<<agg_blocks + ow_tail, 128>>>(
        (const __half*)h0_p, (__half*)hin_p, ps0, gamma_0, beta_0, out,
        invN, N, G, agg_blocks);
    mlp_kernel<false><<<mlp_blocks, 128, MLP_SMEM_BYTES>>>(
        (const __half*)hin_p, W1_1, b1_1, W2_1, b2_1, batch,
        nullptr, ps1, N);
    outwrite_kernel<<<ow_blocks, 256>>>(ps1, gamma_1, beta_1, out, 64, invN, G);
}